// round 14
// baseline (speedup 1.0000x reference)
#include <cuda_runtime.h>
#include <cuda_bf16.h>
#include <cstdint>

// ---------------------------------------------------------------------------
// GAT layer, algebraically reduced:
//   Sum_{e: src=n} alpha[e,h] == 1{outdeg(n)>0} in fp32
//   => out = (h_in @ W.T + b) * outdeg_mask
//
// mma.sync.m16n8k16 bf16, 3-term split h1w1 + h2w1 + h1w2 (fp32 accum).
// R13: NO smem staging. A fragments are loaded directly from global with
// per-lane LDG.64 in exact fragment layout (q=lane>>2, tig=lane&3):
//   a0=A[q][k0..k0+1] a1=A[q+8][k0..] a2=A[q][k0+8..] a3=A[q+8][k0+8..]
// fp32->bf16 split in registers. Zero barriers; full-tile MLP.
// ---------------------------------------------------------------------------

#define MASK_CAP (1 << 20)
__device__ unsigned char g_mask[MASK_CAP];        // generic fallback
__device__ unsigned int  g_m16[MASK_CAP / 16];    // fast path: 16 rows/word
// B fragments: [split(2)][kiter(8)][nbpair(2)][lane(32)] -> uint4
__device__ uint4 g_B4[2 * 8 * 2 * 32];

// cvt two fp32 -> packed bf16x2 (lo = first arg in low 16 bits)
__device__ __forceinline__ unsigned cvt2bf(float lo, float hi) {
    unsigned r;
    asm("cvt.rn.bf16x2.f32 %0, %1, %2;" : "=r"(r) : "f"(hi), "f"(lo));
    return r;
}
__device__ __forceinline__ float bf_lo(unsigned p) { return __uint_as_float(p << 16); }
__device__ __forceinline__ float bf_hi(unsigned p) { return __uint_as_float(p & 0xffff0000u); }

__device__ __forceinline__ void mma_bf16(float c[4], const unsigned a[4],
                                         unsigned b0, unsigned b1) {
    asm volatile("mma.sync.aligned.m16n8k16.row.col.f32.bf16.bf16.f32 "
                 "{%0,%1,%2,%3}, {%4,%5,%6,%7}, {%8,%9}, {%0,%1,%2,%3};"
                 : "+f"(c[0]), "+f"(c[1]), "+f"(c[2]), "+f"(c[3])
                 : "r"(a[0]), "r"(a[1]), "r"(a[2]), "r"(a[3]), "r"(b0), "r"(b1));
}
// bytes (0/1) of v -> 4 bits
__device__ __forceinline__ unsigned nibb(unsigned v) {
    return (((v & 0x01010101u) * 0x01020408u) >> 24) & 0xFu;
}

// ---------------------------------------------------------------------------
// K1: scatter src -> 16-bit mask words; CTA 0 prepares B fragment pairs.
// ---------------------------------------------------------------------------
__global__ __launch_bounds__(256) void scatter_prep_kernel(
    const int* __restrict__ src, int E, int n, int mapBytes,
    const float* __restrict__ W)
{
    extern __shared__ __align__(16) char dsm[];
    const int tid = threadIdx.x;
    const int g   = gridDim.x;

    if (blockIdx.x == 0) {
        for (int idx = tid; idx < 2 * 8 * 2 * 32; idx += 256) {
            int s    = idx >> 9;
            int t    = (idx >> 6) & 7;
            int p    = (idx >> 5) & 1;
            int lane = idx & 31;
            unsigned fr[2][2];
            #pragma unroll
            for (int i = 0; i < 2; ++i) {
                int nb = 2 * p + i;
                int nj = nb * 8 + (lane >> 2);
                int kk = t * 16 + (lane & 3) * 2;
                #pragma unroll
                for (int r = 0; r < 2; ++r) {
                    int k = kk + r * 8;
                    float x0 = W[nj * 128 + k];
                    float x1 = W[nj * 128 + k + 1];
                    unsigned p1 = cvt2bf(x0, x1);
                    fr[i][r] = (s == 0) ? p1
                             : cvt2bf(x0 - bf_lo(p1), x1 - bf_hi(p1));
                }
            }
            g_B4[idx] = make_uint4(fr[0][0], fr[0][1], fr[1][0], fr[1][1]);
        }
    }

    // zero private byte map
    {
        int4* m4 = reinterpret_cast<int4*>(dsm);
        const int nm4 = mapBytes >> 4;
        for (int i = tid; i < nm4; i += 256) m4[i] = make_int4(0, 0, 0, 0);
    }
    __syncthreads();

    // scatter contiguous edge chunk (plain byte STS)
    {
        const int E4  = E >> 2;
        const int per = (E4 + g - 1) / g;
        const int s4  = blockIdx.x * per;
        const int e4  = min(s4 + per, E4);
        const int4* __restrict__ sp = reinterpret_cast<const int4*>(src);
        for (int i = s4 + tid; i < e4; i += 256) {
            int4 s = sp[i];
            if ((unsigned)s.x < (unsigned)n) dsm[s.x] = 1;
            if ((unsigned)s.y < (unsigned)n) dsm[s.y] = 1;
            if ((unsigned)s.z < (unsigned)n) dsm[s.z] = 1;
            if ((unsigned)s.w < (unsigned)n) dsm[s.w] = 1;
        }
        if (blockIdx.x == g - 1) {
            for (int i = (E4 << 2) + tid; i < E; i += 256) {
                int s = src[i];
                if ((unsigned)s < (unsigned)n) dsm[s] = 1;
            }
        }
    }
    __syncthreads();

    // bit-pack: one 16-bit word per 16 nodes + merge
    {
        const int nW = (n + 15) >> 4;
        const uint4* mv = reinterpret_cast<const uint4*>(dsm);
        for (int w = tid; w < nW; w += 256) {
            uint4 a = mv[w];
            unsigned bits = nibb(a.x) | (nibb(a.y) << 4)
                          | (nibb(a.z) << 8) | (nibb(a.w) << 12);
            if (bits) atomicOr(&g_m16[w], bits);
        }
    }
}

// ---------------------------------------------------------------------------
// K2: register-direct mma.sync GEMM. Tile = 64 rows x 32 cols, 128 threads,
// warp w owns rows w*16..w*16+15. NO shared memory, NO barriers.
// All 32 A LDG.64s issue up front (full-tile MLP), bf16 split in registers.
// ---------------------------------------------------------------------------
__global__ __launch_bounds__(128) void gemm_mma_kernel(
    const float* __restrict__ h_in,   // [n, 128]
    const float* __restrict__ b,      // [32]
    float* __restrict__ out,          // [n, 32]
    int n)
{
    const int tid  = threadIdx.x;
    const int w    = tid >> 5;
    const int lane = tid & 31;
    const int tile = blockIdx.x;

    const int q   = lane >> 2;            // 0..7
    const int tig = lane & 3;             // 0..3

    int row_lo = tile * 64 + w * 16 + q;
    int row_hi = row_lo + 8;
    int rlo = row_lo < n ? row_lo : n - 1;   // clamp; stores guarded later
    int rhi = row_hi < n ? row_hi : n - 1;

    // float2 views of the two rows, offset by tig*2 floats (= tig float2)
    const float2* __restrict__ pLo =
        reinterpret_cast<const float2*>(h_in) + (size_t)rlo * 64 + tig;
    const float2* __restrict__ pHi =
        reinterpret_cast<const float2*>(h_in) + (size_t)rhi * 64 + tig;

    // ---- issue ALL A loads up front: fa[kt] = {lo_kl, hi_kl, lo_kh, hi_kh} ----
    float2 fa[8][4];
    #pragma unroll
    for (int kt = 0; kt < 8; ++kt) {
        fa[kt][0] = pLo[kt * 8];          // row q,   k = kt*16 + tig*2
        fa[kt][1] = pHi[kt * 8];          // row q+8, k = kt*16 + tig*2
        fa[kt][2] = pLo[kt * 8 + 4];      // row q,   k = kt*16 + tig*2 + 8
        fa[kt][3] = pHi[kt * 8 + 4];      // row q+8, k = kt*16 + tig*2 + 8
    }

    // ---- overlap: mask word + bias while loads are in flight ----
    unsigned mword = 0;
    {
        const int widx = tile * 4 + w;
        if (lane == 0) {
            mword = g_m16[widx];
            g_m16[widx] = 0;              // self-clean for next graph replay
        }
        mword = __shfl_sync(0xffffffffu, mword, 0);
    }
    float bsr[4][2];
    #pragma unroll
    for (int nb = 0; nb < 4; ++nb) {
        int c = nb * 8 + tig * 2;
        bsr[nb][0] = b[c];
        bsr[nb][1] = b[c + 1];
    }

    // ---- mainloop: convert in regs + 12 MMAs per k-iter ----
    float acc[4][4] = {};
    const uint4* __restrict__ Bp = g_B4 + lane;

    #pragma unroll
    for (int kt = 0; kt < 8; ++kt) {
        unsigned a1[4], a2[4];
        #pragma unroll
        for (int j = 0; j < 4; ++j) {
            float2 f = fa[kt][j];
            unsigned p1 = cvt2bf(f.x, f.y);                 // h1 fragment
            a1[j] = p1;
            a2[j] = cvt2bf(f.x - bf_lo(p1), f.y - bf_hi(p1)); // h2 fragment
        }
        uint4 b10 = Bp[(kt * 2 + 0) * 32];        // w1, nb {0,1}
        uint4 b11 = Bp[(kt * 2 + 1) * 32];        // w1, nb {2,3}
        uint4 b20 = Bp[(16 + kt * 2 + 0) * 32];   // w2, nb {0,1}
        uint4 b21 = Bp[(16 + kt * 2 + 1) * 32];   // w2, nb {2,3}
        mma_bf16(acc[0], a1, b10.x, b10.y);       // h1*w1
        mma_bf16(acc[1], a1, b10.z, b10.w);
        mma_bf16(acc[2], a1, b11.x, b11.y);
        mma_bf16(acc[3], a1, b11.z, b11.w);
        mma_bf16(acc[0], a2, b10.x, b10.y);       // h2*w1
        mma_bf16(acc[1], a2, b10.z, b10.w);
        mma_bf16(acc[2], a2, b11.x, b11.y);
        mma_bf16(acc[3], a2, b11.z, b11.w);
        mma_bf16(acc[0], a1, b20.x, b20.y);       // h1*w2
        mma_bf16(acc[1], a1, b20.z, b20.w);
        mma_bf16(acc[2], a1, b21.x, b21.y);
        mma_bf16(acc[3], a1, b21.z, b21.w);
    }

    // ---- epilogue: bias + mask + STG.64 ----
    {
        const float m0 = ((mword >> q) & 1u) ? 1.0f : 0.0f;
        const float m1 = ((mword >> (q + 8)) & 1u) ? 1.0f : 0.0f;
        #pragma unroll
        for (int nb = 0; nb < 4; ++nb) {
            const int c = nb * 8 + tig * 2;
            if (row_lo < n) {
                float2 v = make_float2((acc[nb][0] + bsr[nb][0]) * m0,
                                       (acc[nb][1] + bsr[nb][1]) * m0);
                *reinterpret_cast<float2*>(out + (size_t)row_lo * 32 + c) = v;
            }
            if (row_hi < n) {
                float2 v = make_float2((acc[nb][2] + bsr[nb][0]) * m1,
                                       (acc[nb][3] + bsr[nb][1]) * m1);
                *reinterpret_cast<float2*>(out + (size_t)row_hi * 32 + c) = v;
            }
        }
    }
}

// ---------------------------------------------------------------------------
// Generic fallbacks (any dims) — correctness insurance only.
// ---------------------------------------------------------------------------
__global__ void generic_scatter_kernel(const int* __restrict__ src, int E) {
    int i = blockIdx.x * blockDim.x + threadIdx.x;
    int stride = gridDim.x * blockDim.x;
    for (int e = i; e < E; e += stride) g_mask[src[e]] = 1;
}
__global__ void generic_gemm_kernel(
    const float* __restrict__ h_in, const float* __restrict__ W,
    const float* __restrict__ b, float* __restrict__ out,
    int n, int f_in, int hf)
{
    long long idx = (long long)blockIdx.x * blockDim.x + threadIdx.x;
    if (idx >= (long long)n * hf) return;
    int node = (int)(idx / hf);
    int j    = (int)(idx % hf);
    const float* hr = h_in + (size_t)node * f_in;
    const float* wr = W + (size_t)j * f_in;
    float acc = b[j];
    for (int k = 0; k < f_in; ++k) acc += hr[k] * wr[k];
    out[idx] = acc;
}
__global__ void generic_maskfix_kernel(float* __restrict__ out, int n, int hf) {
    int i = blockIdx.x * blockDim.x + threadIdx.x;
    if (i >= n) return;
    unsigned char m = g_mask[i];
    g_mask[i] = 0;
    if (!m) {
        float* o = out + (size_t)i * hf;
        for (int j = 0; j < hf; ++j) o[j] = 0.0f;
    }
}

extern "C" void kernel_launch(void* const* d_in, const int* in_sizes, int n_in,
                              void* d_out, int out_size) {
    const float* h_in = (const float*)d_in[0];
    const float* W    = (const float*)d_in[1];
    const float* b    = (const float*)d_in[2];
    // d_in[3]=a_src, d_in[4]=a_tgt: provably unused after reduction
    const int* edge_index = (const int*)d_in[5];

    int HF   = in_sizes[2];               // H * F_OUT
    int F_IN = in_sizes[1] / HF;
    int n    = in_sizes[0] / F_IN;
    int E    = in_sizes[5] / 2;
    const int* src = edge_index;          // row 0 of [2, E]

    float* out = (float*)d_out;

    if (F_IN == 128 && HF == 32 && n <= 102400) {
        int mapBytes = (n + 127) & ~127;

        static int sm_count = 0;
        if (sm_count == 0) {
            cudaDeviceGetAttribute(&sm_count, cudaDevAttrMultiProcessorCount, 0);
            cudaFuncSetAttribute(scatter_prep_kernel,
                                 cudaFuncAttributeMaxDynamicSharedMemorySize, 104000);
        }

        scatter_prep_kernel<<<sm_count, 256, mapBytes>>>(src, E, n, mapBytes, W);
        int tiles = (n + 63) / 64;
        gemm_mma_kernel<<<tiles, 128>>>(h_in, b, out, n);
    } else {
        generic_scatter_kernel<<<1024, 256>>>(src, E);
        long long total = (long long)n * HF;
        generic_gemm_kernel<<<(int)((total + 255) / 256), 256>>>(
            h_in, W, b, out, n, F_IN, HF);
        generic_maskfix_kernel<<<(n + 255) / 256, 256>>>(out, n, HF);
    }
    (void)n_in; (void)out_size;
}

// round 15
// speedup vs baseline: 1.5286x; 1.5286x over previous
#include <cuda_runtime.h>
#include <cuda_bf16.h>
#include <cstdint>

// ---------------------------------------------------------------------------
// GAT layer, algebraically reduced:
//   Sum_{e: src=n} alpha[e,h] == 1{outdeg(n)>0} in fp32
//   => out = (h_in @ W.T + b) * outdeg_mask
//
// mma.sync.m16n8k16 bf16, 3-term split h1w1 + h2w1 + h1w2 (fp32 accum).
// R13 lesson: register-direct A loads get re-sunk by ptxas into dependent
// chains (regs=56, issue 11%) + anti-coalesced. cp.async->smem->ldmatrix is
// the right A path. R14 = R10 (best, 27.1us) + progressive convert:
// 4 cp.async commit-groups of 4 rows, convert group g under wait_group(3-g)
// so conversion overlaps DRAM flight and the mainloop starts earlier.
// ---------------------------------------------------------------------------

#define MASK_CAP (1 << 20)
__device__ unsigned char g_mask[MASK_CAP];        // generic fallback
__device__ unsigned int  g_m16[MASK_CAP / 16];    // fast path: 16 rows/word
// B fragments: [split(2)][kiter(8)][nbpair(2)][lane(32)] -> uint4
__device__ uint4 g_B4[2 * 8 * 2 * 32];

// cvt two fp32 -> packed bf16x2 (lo = first arg in low 16 bits)
__device__ __forceinline__ unsigned cvt2bf(float lo, float hi) {
    unsigned r;
    asm("cvt.rn.bf16x2.f32 %0, %1, %2;" : "=r"(r) : "f"(hi), "f"(lo));
    return r;
}
__device__ __forceinline__ float bf_lo(unsigned p) { return __uint_as_float(p << 16); }
__device__ __forceinline__ float bf_hi(unsigned p) { return __uint_as_float(p & 0xffff0000u); }

__device__ __forceinline__ void ldsm4(unsigned r[4], uint32_t addr) {
    asm volatile("ldmatrix.sync.aligned.m8n8.x4.shared.b16 {%0,%1,%2,%3}, [%4];"
                 : "=r"(r[0]), "=r"(r[1]), "=r"(r[2]), "=r"(r[3]) : "r"(addr));
}
__device__ __forceinline__ void mma_bf16(float c[4], const unsigned a[4],
                                         unsigned b0, unsigned b1) {
    asm volatile("mma.sync.aligned.m16n8k16.row.col.f32.bf16.bf16.f32 "
                 "{%0,%1,%2,%3}, {%4,%5,%6,%7}, {%8,%9}, {%0,%1,%2,%3};"
                 : "+f"(c[0]), "+f"(c[1]), "+f"(c[2]), "+f"(c[3])
                 : "r"(a[0]), "r"(a[1]), "r"(a[2]), "r"(a[3]), "r"(b0), "r"(b1));
}
__device__ __forceinline__ uint32_t smem_u32(const void* p) {
    uint32_t a;
    asm("{ .reg .u64 t; cvta.to.shared.u64 t, %1; cvt.u32.u64 %0, t; }"
        : "=r"(a) : "l"(p));
    return a;
}
// bytes (0/1) of v -> 4 bits
__device__ __forceinline__ unsigned nibb(unsigned v) {
    return (((v & 0x01010101u) * 0x01020408u) >> 24) & 0xFu;
}

// ---------------------------------------------------------------------------
// K1: scatter src -> 16-bit mask words; CTA 0 prepares B fragment pairs.
// ---------------------------------------------------------------------------
__global__ __launch_bounds__(256) void scatter_prep_kernel(
    const int* __restrict__ src, int E, int n, int mapBytes,
    const float* __restrict__ W)
{
    extern __shared__ __align__(16) char dsm[];
    const int tid = threadIdx.x;
    const int g   = gridDim.x;

    if (blockIdx.x == 0) {
        for (int idx = tid; idx < 2 * 8 * 2 * 32; idx += 256) {
            int s    = idx >> 9;
            int t    = (idx >> 6) & 7;
            int p    = (idx >> 5) & 1;
            int lane = idx & 31;
            unsigned fr[2][2];
            #pragma unroll
            for (int i = 0; i < 2; ++i) {
                int nb = 2 * p + i;
                int nj = nb * 8 + (lane >> 2);
                int kk = t * 16 + (lane & 3) * 2;
                #pragma unroll
                for (int r = 0; r < 2; ++r) {
                    int k = kk + r * 8;
                    float x0 = W[nj * 128 + k];
                    float x1 = W[nj * 128 + k + 1];
                    unsigned p1 = cvt2bf(x0, x1);
                    fr[i][r] = (s == 0) ? p1
                             : cvt2bf(x0 - bf_lo(p1), x1 - bf_hi(p1));
                }
            }
            g_B4[idx] = make_uint4(fr[0][0], fr[0][1], fr[1][0], fr[1][1]);
        }
    }

    // zero private byte map
    {
        int4* m4 = reinterpret_cast<int4*>(dsm);
        const int nm4 = mapBytes >> 4;
        for (int i = tid; i < nm4; i += 256) m4[i] = make_int4(0, 0, 0, 0);
    }
    __syncthreads();

    // scatter contiguous edge chunk (plain byte STS)
    {
        const int E4  = E >> 2;
        const int per = (E4 + g - 1) / g;
        const int s4  = blockIdx.x * per;
        const int e4  = min(s4 + per, E4);
        const int4* __restrict__ sp = reinterpret_cast<const int4*>(src);
        for (int i = s4 + tid; i < e4; i += 256) {
            int4 s = sp[i];
            if ((unsigned)s.x < (unsigned)n) dsm[s.x] = 1;
            if ((unsigned)s.y < (unsigned)n) dsm[s.y] = 1;
            if ((unsigned)s.z < (unsigned)n) dsm[s.z] = 1;
            if ((unsigned)s.w < (unsigned)n) dsm[s.w] = 1;
        }
        if (blockIdx.x == g - 1) {
            for (int i = (E4 << 2) + tid; i < E; i += 256) {
                int s = src[i];
                if ((unsigned)s < (unsigned)n) dsm[s] = 1;
            }
        }
    }
    __syncthreads();

    // bit-pack: one 16-bit word per 16 nodes + merge
    {
        const int nW = (n + 15) >> 4;
        const uint4* mv = reinterpret_cast<const uint4*>(dsm);
        for (int w = tid; w < nW; w += 256) {
            uint4 a = mv[w];
            unsigned bits = nibb(a.x) | (nibb(a.y) << 4)
                          | (nibb(a.z) << 8) | (nibb(a.w) << 12);
            if (bits) atomicOr(&g_m16[w], bits);
        }
    }
}

// ---------------------------------------------------------------------------
// K2: mma.sync GEMM. Tile = 64 rows x 32 cols, 128 threads.
// Warp w owns rows w*16..w*16+15 (cp.async + convert + mainloop + epilogue
// all warp-private). cp.async in 4 commit-groups of 4 rows; convert group g
// under wait_group(3-g) so conversion overlaps the remaining DRAM flight.
// A smem: [row][h1 256B | h2 256B], pitch 512B, XOR-(row&7)<<4 swizzle on
// the full byte offset. One early __syncthreads (bias+mask publish only).
// ---------------------------------------------------------------------------
__global__ __launch_bounds__(128) void gemm_mma_kernel(
    const float* __restrict__ h_in,   // [n, 128]
    const float* __restrict__ b,      // [32]
    float* __restrict__ out,          // [n, 32]
    int n)
{
    __shared__ __align__(16) unsigned char As[64 * 512];   // 32KB
    __shared__ float bs[32];
    __shared__ unsigned mb[4];

    const int tid  = threadIdx.x;
    const int w    = tid >> 5;
    const int lane = tid & 31;
    const int tile = blockIdx.x;
    const uint32_t As_b = smem_u32(As);

    // ---- phase 1: cp.async own 16 rows in 4 commit-groups of 4 rows ----
    #pragma unroll
    for (int grp = 0; grp < 4; ++grp) {
        #pragma unroll
        for (int it = 0; it < 4; ++it) {
            int row = w * 16 + grp * 4 + it;
            int gr  = tile * 64 + row;
            if (gr >= n) gr = n - 1;       // clamp; stores guarded later
            const char* srcp = reinterpret_cast<const char*>(h_in) +
                               (size_t)gr * 512 + (size_t)(lane * 16);
            uint32_t dst = As_b +
                ((((uint32_t)(row * 512)) + (uint32_t)(lane * 16)) ^
                 ((uint32_t)((row & 7) << 4)));
            asm volatile("cp.async.cg.shared.global [%0], [%1], 16;"
                         :: "r"(dst), "l"(srcp) : "memory");
        }
        asm volatile("cp.async.commit_group;" ::: "memory");
    }

    // publish bias + mask words; barrier does NOT wait on the async copies
    if (tid < 32) bs[tid] = b[tid];
    if (tid < 4) {
        int wi = tile * 4 + tid;
        mb[tid] = g_m16[wi];
        g_m16[wi] = 0;                     // self-clean for next graph replay
    }
    __syncthreads();

    // ---- phase 2: progressive wait + in-place convert (4 rows per group) ----
    #pragma unroll
    for (int grp = 0; grp < 4; ++grp) {
        if (grp == 0)      asm volatile("cp.async.wait_group 3;" ::: "memory");
        else if (grp == 1) asm volatile("cp.async.wait_group 2;" ::: "memory");
        else if (grp == 2) asm volatile("cp.async.wait_group 1;" ::: "memory");
        else               asm volatile("cp.async.wait_group 0;" ::: "memory");
        #pragma unroll
        for (int it = 0; it < 4; ++it) {
            int row = w * 16 + grp * 4 + it;
            uint32_t sw = (uint32_t)((row & 7) << 4);
            uint32_t ro = (uint32_t)(row * 512);
            float4 f4;
            asm volatile("ld.shared.v4.f32 {%0,%1,%2,%3}, [%4];"
                         : "=f"(f4.x), "=f"(f4.y), "=f"(f4.z), "=f"(f4.w)
                         : "r"(As_b + ((ro + (uint32_t)(lane * 16)) ^ sw)));
            unsigned p1a = cvt2bf(f4.x, f4.y);
            unsigned p1b = cvt2bf(f4.z, f4.w);
            unsigned p2a = cvt2bf(f4.x - bf_lo(p1a), f4.y - bf_hi(p1a));
            unsigned p2b = cvt2bf(f4.z - bf_lo(p1b), f4.w - bf_hi(p1b));
            unsigned long long v1 =
                (unsigned long long)p1a | ((unsigned long long)p1b << 32);
            unsigned long long v2 =
                (unsigned long long)p2a | ((unsigned long long)p2b << 32);
            asm volatile("st.shared.b64 [%0], %1;"
                         :: "r"(As_b + ((ro + (uint32_t)(lane * 8)) ^ sw)), "l"(v1)
                         : "memory");
            asm volatile("st.shared.b64 [%0], %1;"
                         :: "r"(As_b + ((ro + 256u + (uint32_t)(lane * 8)) ^ sw)), "l"(v2)
                         : "memory");
        }
    }
    __syncwarp();   // converted rows visible to ldmatrix within the warp

    // ---- mainloop: warp-private, 8 k-iters, 4 n-blocks, 3 split phases ----
    float acc[4][4] = {};

    const uint32_t colh = (uint32_t)((lane >> 4) << 4);
    const uint32_t swz  = (uint32_t)((lane & 7) << 4);
    const int rowl = w * 16 + (lane & 15);
    const uint32_t aoff = (uint32_t)(rowl * 512) + colh;
    const uint4* __restrict__ Bp = g_B4 + lane;

    #pragma unroll
    for (int kt = 0; kt < 8; ++kt) {
        unsigned a1[4], a2[4];
        ldsm4(a1, As_b + ((aoff + (uint32_t)(kt * 32)) ^ swz));         // h1
        ldsm4(a2, As_b + ((aoff + (uint32_t)(256 + kt * 32)) ^ swz));   // h2
        uint4 b10 = Bp[(kt * 2 + 0) * 32];        // w1, nb {0,1}
        uint4 b11 = Bp[(kt * 2 + 1) * 32];        // w1, nb {2,3}
        uint4 b20 = Bp[(16 + kt * 2 + 0) * 32];   // w2, nb {0,1}
        uint4 b21 = Bp[(16 + kt * 2 + 1) * 32];   // w2, nb {2,3}
        mma_bf16(acc[0], a1, b10.x, b10.y);       // h1*w1
        mma_bf16(acc[1], a1, b10.z, b10.w);
        mma_bf16(acc[2], a1, b11.x, b11.y);
        mma_bf16(acc[3], a1, b11.z, b11.w);
        mma_bf16(acc[0], a2, b10.x, b10.y);       // h2*w1
        mma_bf16(acc[1], a2, b10.z, b10.w);
        mma_bf16(acc[2], a2, b11.x, b11.y);
        mma_bf16(acc[3], a2, b11.z, b11.w);
        mma_bf16(acc[0], a1, b20.x, b20.y);       // h1*w2
        mma_bf16(acc[1], a1, b20.z, b20.w);
        mma_bf16(acc[2], a1, b21.x, b21.y);
        mma_bf16(acc[3], a1, b21.z, b21.w);
    }

    // ---- epilogue: bias + mask + STG.64 ----
    {
        const unsigned mword = mb[w];              // warp-uniform 16-bit word
        const int rt0 = lane >> 2;                 // 0..7 within warp rows
        const int r0  = tile * 64 + w * 16 + rt0;
        const int r1  = r0 + 8;
        const float m0 = ((mword >> rt0) & 1u) ? 1.0f : 0.0f;
        const float m1 = ((mword >> (rt0 + 8)) & 1u) ? 1.0f : 0.0f;
        #pragma unroll
        for (int nb = 0; nb < 4; ++nb) {
            const int c = nb * 8 + (lane & 3) * 2;
            if (r0 < n) {
                float2 v = make_float2((acc[nb][0] + bs[c]) * m0,
                                       (acc[nb][1] + bs[c + 1]) * m0);
                *reinterpret_cast<float2*>(out + (size_t)r0 * 32 + c) = v;
            }
            if (r1 < n) {
                float2 v = make_float2((acc[nb][2] + bs[c]) * m1,
                                       (acc[nb][3] + bs[c + 1]) * m1);
                *reinterpret_cast<float2*>(out + (size_t)r1 * 32 + c) = v;
            }
        }
    }
}

// ---------------------------------------------------------------------------
// Generic fallbacks (any dims) — correctness insurance only.
// ---------------------------------------------------------------------------
__global__ void generic_scatter_kernel(const int* __restrict__ src, int E) {
    int i = blockIdx.x * blockDim.x + threadIdx.x;
    int stride = gridDim.x * blockDim.x;
    for (int e = i; e < E; e += stride) g_mask[src[e]] = 1;
}
__global__ void generic_gemm_kernel(
    const float* __restrict__ h_in, const float* __restrict__ W,
    const float* __restrict__ b, float* __restrict__ out,
    int n, int f_in, int hf)
{
    long long idx = (long long)blockIdx.x * blockDim.x + threadIdx.x;
    if (idx >= (long long)n * hf) return;
    int node = (int)(idx / hf);
    int j    = (int)(idx % hf);
    const float* hr = h_in + (size_t)node * f_in;
    const float* wr = W + (size_t)j * f_in;
    float acc = b[j];
    for (int k = 0; k < f_in; ++k) acc += hr[k] * wr[k];
    out[idx] = acc;
}
__global__ void generic_maskfix_kernel(float* __restrict__ out, int n, int hf) {
    int i = blockIdx.x * blockDim.x + threadIdx.x;
    if (i >= n) return;
    unsigned char m = g_mask[i];
    g_mask[i] = 0;
    if (!m) {
        float* o = out + (size_t)i * hf;
        for (int j = 0; j < hf; ++j) o[j] = 0.0f;
    }
}

extern "C" void kernel_launch(void* const* d_in, const int* in_sizes, int n_in,
                              void* d_out, int out_size) {
    const float* h_in = (const float*)d_in[0];
    const float* W    = (const float*)d_in[1];
    const float* b    = (const float*)d_in[2];
    // d_in[3]=a_src, d_in[4]=a_tgt: provably unused after reduction
    const int* edge_index = (const int*)d_in[5];

    int HF   = in_sizes[2];               // H * F_OUT
    int F_IN = in_sizes[1] / HF;
    int n    = in_sizes[0] / F_IN;
    int E    = in_sizes[5] / 2;
    const int* src = edge_index;          // row 0 of [2, E]

    float* out = (float*)d_out;

    if (F_IN == 128 && HF == 32 && n <= 102400) {
        int mapBytes = (n + 127) & ~127;

        static int sm_count = 0;
        if (sm_count == 0) {
            cudaDeviceGetAttribute(&sm_count, cudaDevAttrMultiProcessorCount, 0);
            cudaFuncSetAttribute(scatter_prep_kernel,
                                 cudaFuncAttributeMaxDynamicSharedMemorySize, 104000);
        }

        scatter_prep_kernel<<<sm_count, 256, mapBytes>>>(src, E, n, mapBytes, W);
        int tiles = (n + 63) / 64;
        gemm_mma_kernel<<<tiles, 128>>>(h_in, b, out, n);
    } else {
        generic_scatter_kernel<<<1024, 256>>>(src, E);
        long long total = (long long)n * HF;
        generic_gemm_kernel<<<(int)((total + 255) / 256), 256>>>(
            h_in, W, b, out, n, F_IN, HF);
        generic_maskfix_kernel<<<(n + 255) / 256, 256>>>(out, n, HF);
    }
    (void)n_in; (void)out_size;
}